// round 4
// baseline (speedup 1.0000x reference)
#include <cuda_runtime.h>

#define M 512
#define KMAX 131072
#define GRID 296      // 2 CTAs/SM even on 148 SMs -> all co-resident (barrier-safe)

// Scratch (__device__ globals, zero-initialized at load).
// Cleanup-at-end protocol: last CTA re-zeros everything it accumulated so each
// graph replay starts from a clean state.
__device__ float    g_t[KMAX];     // t_k
__device__ float    g_v1[M];       // W^T a1 (atomic accum)
__device__ float    g_v2[M];       // W^T a2 (atomic accum)
__device__ float    g_colsum[M];   // column sums of x
__device__ float    g_scal[4];     // [0]=c1+c2, [1]=C, [2]=Z
__device__ unsigned g_cA, g_relA;  // barrier A (after v1/v2 accumulation)
__device__ unsigned g_cB, g_relB;  // barrier B (after pass1, C ready)
__device__ unsigned g_cnt2;        // final completion counter

__global__ __launch_bounds__(256, 2) void mhi_fused(const float* __restrict__ x,
                                                    const float* __restrict__ W,
                                                    const float* __restrict__ b,
                                                    const float* __restrict__ a,
                                                    float* __restrict__ out, int K) {
    int tid  = threadIdx.x;
    int lane = tid & 31, w = tid >> 5;
    int bid  = blockIdx.x;

    // ---------------- Phase 0: v1 += W^T a1, v2 += W^T a2 ; c12 ; zero out ----
    if (bid < 256) {
        // CTA covers W rows [2*bid, 2*bid+1]; each thread: one float4 of one row.
        int row = bid * 2 + (tid >> 7);
        int c4  = tid & 127;
        float4 w4 = reinterpret_cast<const float4*>(W)[row * 128 + c4];
        float A1 = __ldg(a + row);
        float A2 = __ldg(a + M + row);
        int j = c4 * 4;
        atomicAdd(&g_v1[j + 0], A1 * w4.x); atomicAdd(&g_v1[j + 1], A1 * w4.y);
        atomicAdd(&g_v1[j + 2], A1 * w4.z); atomicAdd(&g_v1[j + 3], A1 * w4.w);
        atomicAdd(&g_v2[j + 0], A2 * w4.x); atomicAdd(&g_v2[j + 1], A2 * w4.y);
        atomicAdd(&g_v2[j + 2], A2 * w4.z); atomicAdd(&g_v2[j + 3], A2 * w4.w);
    } else if (bid == 256) {
        out[tid]       = 0.f;   // d_out is poisoned: zero before pass2 atomics
        out[tid + 256] = 0.f;
        float p1 = 0.f, p2 = 0.f;
        for (int i = tid; i < M; i += 256) {
            p1 += b[i] * a[i];
            p2 += b[i] * a[M + i];
        }
        #pragma unroll
        for (int o = 16; o; o >>= 1) {
            p1 += __shfl_xor_sync(0xFFFFFFFFu, p1, o);
            p2 += __shfl_xor_sync(0xFFFFFFFFu, p2, o);
        }
        __shared__ float rb[16];
        if (lane == 0) { rb[w] = p1; rb[8 + w] = p2; }
        __syncthreads();
        if (tid == 0) {
            float s = 0.f;
            #pragma unroll
            for (int q = 0; q < 16; q++) s += rb[q];
            g_scal[0] = s;      // c1 + c2
        }
    }

    // ---------------- Barrier A --------------------------------------------
    __threadfence();
    __syncthreads();
    if (tid == 0) {
        if (atomicAdd(&g_cA, 1u) == GRID - 1) {
            atomicExch(&g_relA, 1u);
        } else {
            while (atomicAdd(&g_relA, 0u) == 0u) __nanosleep(64);
        }
    }
    __syncthreads();
    __threadfence();

    // ---------------- Pass 1 (ascending): t_k = x_k.v1 ; colsum ------------
    __shared__ float4 sv[M / 4];
    __shared__ float  scol[M];
    if (tid < M / 4) sv[tid] = reinterpret_cast<const float4*>(g_v1)[tid];
    for (int j = tid; j < M; j += 256) scol[j] = 0.f;
    __syncthreads();

    float4 v0 = sv[lane], v1 = sv[lane + 32], v2 = sv[lane + 64], v3 = sv[lane + 96];
    float4 a0 = {0,0,0,0}, a1 = a0, a2 = a0, a3 = a0;
    int gw = bid * 8 + w;
    int nw = GRID * 8;
    for (int k = gw * 2; k < K; k += nw * 2) {
        const float4* rA = reinterpret_cast<const float4*>(x + (size_t)k * M);
        float4 x0 = rA[lane], x1 = rA[lane + 32], x2 = rA[lane + 64], x3 = rA[lane + 96];
        bool hasB = (k + 1) < K;
        const float4* rB = reinterpret_cast<const float4*>(x + (size_t)(hasB ? k + 1 : k) * M);
        float4 y0 = rB[lane], y1 = rB[lane + 32], y2 = rB[lane + 64], y3 = rB[lane + 96];

        float dA = x0.x*v0.x + x0.y*v0.y + x0.z*v0.z + x0.w*v0.w
                 + x1.x*v1.x + x1.y*v1.y + x1.z*v1.z + x1.w*v1.w
                 + x2.x*v2.x + x2.y*v2.y + x2.z*v2.z + x2.w*v2.w
                 + x3.x*v3.x + x3.y*v3.y + x3.z*v3.z + x3.w*v3.w;
        float dB = y0.x*v0.x + y0.y*v0.y + y0.z*v0.z + y0.w*v0.w
                 + y1.x*v1.x + y1.y*v1.y + y1.z*v1.z + y1.w*v1.w
                 + y2.x*v2.x + y2.y*v2.y + y2.z*v2.z + y2.w*v2.w
                 + y3.x*v3.x + y3.y*v3.y + y3.z*v3.z + y3.w*v3.w;
        #pragma unroll
        for (int o = 16; o; o >>= 1) {
            dA += __shfl_xor_sync(0xFFFFFFFFu, dA, o);
            dB += __shfl_xor_sync(0xFFFFFFFFu, dB, o);
        }
        if (lane == 0) {
            g_t[k] = dA;
            if (hasB) g_t[k + 1] = dB;
        }
        a0.x += x0.x; a0.y += x0.y; a0.z += x0.z; a0.w += x0.w;
        a1.x += x1.x; a1.y += x1.y; a1.z += x1.z; a1.w += x1.w;
        a2.x += x2.x; a2.y += x2.y; a2.z += x2.z; a2.w += x2.w;
        a3.x += x3.x; a3.y += x3.y; a3.z += x3.z; a3.w += x3.w;
        if (hasB) {
            a0.x += y0.x; a0.y += y0.y; a0.z += y0.z; a0.w += y0.w;
            a1.x += y1.x; a1.y += y1.y; a1.z += y1.z; a1.w += y1.w;
            a2.x += y2.x; a2.y += y2.y; a2.z += y2.z; a2.w += y2.w;
            a3.x += y3.x; a3.y += y3.y; a3.z += y3.z; a3.w += y3.w;
        }
    }
    {
        int c = 4 * lane;
        atomicAdd(&scol[c + 0],       a0.x); atomicAdd(&scol[c + 1],       a0.y);
        atomicAdd(&scol[c + 2],       a0.z); atomicAdd(&scol[c + 3],       a0.w);
        atomicAdd(&scol[128 + c + 0], a1.x); atomicAdd(&scol[128 + c + 1], a1.y);
        atomicAdd(&scol[128 + c + 2], a1.z); atomicAdd(&scol[128 + c + 3], a1.w);
        atomicAdd(&scol[256 + c + 0], a2.x); atomicAdd(&scol[256 + c + 1], a2.y);
        atomicAdd(&scol[256 + c + 2], a2.z); atomicAdd(&scol[256 + c + 3], a2.w);
        atomicAdd(&scol[384 + c + 0], a3.x); atomicAdd(&scol[384 + c + 1], a3.y);
        atomicAdd(&scol[384 + c + 2], a3.z); atomicAdd(&scol[384 + c + 3], a3.w);
    }
    __syncthreads();
    for (int j = tid; j < M; j += 256) atomicAdd(&g_colsum[j], scol[j]);

    // ---------------- Barrier B: last CTA computes C ------------------------
    __threadfence();
    __syncthreads();
    __shared__ bool lastB;
    if (tid == 0) lastB = (atomicAdd(&g_cB, 1u) == GRID - 1);
    __syncthreads();
    if (lastB) {
        float p = 0.f;
        for (int j = tid; j < M; j += 256) p += g_colsum[j] * g_v2[j];
        #pragma unroll
        for (int o = 16; o; o >>= 1) p += __shfl_xor_sync(0xFFFFFFFFu, p, o);
        __shared__ float sp[8];
        if (lane == 0) sp[w] = p;
        __syncthreads();
        if (tid == 0) {
            float s = 0.f;
            #pragma unroll
            for (int q = 0; q < 8; q++) s += sp[q];
            g_scal[1] = g_scal[0] + s * (1.0f / (float)K);
            __threadfence();
            atomicExch(&g_relB, 1u);
        }
    } else if (tid == 0) {
        while (atomicAdd(&g_relB, 0u) == 0u) __nanosleep(64);
    }
    __syncthreads();
    __threadfence();
    float C = g_scal[1];

    // ---------------- Pass 2 (descending; top of x is L2-hot) --------------
    // w_k = exp(relu(t_k + C)) (softmax shift-invariant; e in [0,~6], safe).
    for (int j = tid; j < M; j += 256) scol[j] = 0.f;
    __syncthreads();
    a0 = make_float4(0,0,0,0); a1 = a0; a2 = a0; a3 = a0;
    float zloc = 0.f;
    int P = (K + 1) >> 1;
    for (int p = P - 1 - gw; p >= 0; p -= nw) {
        int k = 2 * p;
        bool hasB = (k + 1) < K;
        float wA = __expf(fmaxf(g_t[k] + C, 0.f));
        float wB = hasB ? __expf(fmaxf(g_t[k + 1] + C, 0.f)) : 0.f;
        const float4* rA = reinterpret_cast<const float4*>(x + (size_t)k * M);
        float4 x0 = rA[lane], x1 = rA[lane + 32], x2 = rA[lane + 64], x3 = rA[lane + 96];
        const float4* rB = reinterpret_cast<const float4*>(x + (size_t)(hasB ? k + 1 : k) * M);
        float4 y0 = rB[lane], y1 = rB[lane + 32], y2 = rB[lane + 64], y3 = rB[lane + 96];
        a0.x += wA*x0.x + wB*y0.x; a0.y += wA*x0.y + wB*y0.y;
        a0.z += wA*x0.z + wB*y0.z; a0.w += wA*x0.w + wB*y0.w;
        a1.x += wA*x1.x + wB*y1.x; a1.y += wA*x1.y + wB*y1.y;
        a1.z += wA*x1.z + wB*y1.z; a1.w += wA*x1.w + wB*y1.w;
        a2.x += wA*x2.x + wB*y2.x; a2.y += wA*x2.y + wB*y2.y;
        a2.z += wA*x2.z + wB*y2.z; a2.w += wA*x2.w + wB*y2.w;
        a3.x += wA*x3.x + wB*y3.x; a3.y += wA*x3.y + wB*y3.y;
        a3.z += wA*x3.z + wB*y3.z; a3.w += wA*x3.w + wB*y3.w;
        zloc += wA + wB;
    }
    __shared__ float zw[8];
    if (lane == 0) zw[w] = zloc;   // zloc identical across lanes

    {
        int c = 4 * lane;
        atomicAdd(&scol[c + 0],       a0.x); atomicAdd(&scol[c + 1],       a0.y);
        atomicAdd(&scol[c + 2],       a0.z); atomicAdd(&scol[c + 3],       a0.w);
        atomicAdd(&scol[128 + c + 0], a1.x); atomicAdd(&scol[128 + c + 1], a1.y);
        atomicAdd(&scol[128 + c + 2], a1.z); atomicAdd(&scol[128 + c + 3], a1.w);
        atomicAdd(&scol[256 + c + 0], a2.x); atomicAdd(&scol[256 + c + 1], a2.y);
        atomicAdd(&scol[256 + c + 2], a2.z); atomicAdd(&scol[256 + c + 3], a2.w);
        atomicAdd(&scol[384 + c + 0], a3.x); atomicAdd(&scol[384 + c + 1], a3.y);
        atomicAdd(&scol[384 + c + 2], a3.z); atomicAdd(&scol[384 + c + 3], a3.w);
    }
    __syncthreads();
    if (tid == 0) {
        float z = 0.f;
        #pragma unroll
        for (int q = 0; q < 8; q++) z += zw[q];
        atomicAdd(&g_scal[2], z);
    }
    for (int j = tid; j < M; j += 256) atomicAdd(&out[j], scol[j]);

    // ---------------- Finalize: last CTA normalizes and cleans up ----------
    __threadfence();
    __syncthreads();
    __shared__ bool last2;
    if (tid == 0) last2 = (atomicAdd(&g_cnt2, 1u) == GRID - 1);
    __syncthreads();
    if (last2) {
        float invZ = 1.0f / g_scal[2];
        for (int j = tid; j < M; j += 256) {
            out[j] *= invZ;
            g_v1[j] = 0.f; g_v2[j] = 0.f; g_colsum[j] = 0.f;  // replay cleanup
        }
        if (tid == 0) {
            g_scal[2] = 0.f;
            g_cA = 0u; g_relA = 0u; g_cB = 0u; g_relB = 0u; g_cnt2 = 0u;
        }
    }
}

// ---------------------------------------------------------------------------
extern "C" void kernel_launch(void* const* d_in, const int* in_sizes, int n_in,
                              void* d_out, int out_size) {
    const float* x = (const float*)d_in[0];   // [K, 512]
    const float* W = (const float*)d_in[1];   // [512, 512]
    const float* b = (const float*)d_in[2];   // [512]
    const float* a = (const float*)d_in[3];   // [1024]
    float* out = (float*)d_out;               // [512]
    int K = in_sizes[0] / M;

    mhi_fused<<<GRID, 256>>>(x, W, b, a, out, K);
}

// round 6
// speedup vs baseline: 1.0198x; 1.0198x over previous
#include <cuda_runtime.h>
#include <cuda_fp16.h>

#define M 512
#define KMAX 131072
#define PASS_GRID 608   // ~4 CTAs/SM

// bit-cast helpers (no such intrinsics exist for half2<->uint)
__device__ __forceinline__ unsigned h2u(__half2 h) {
    unsigned u; *reinterpret_cast<__half2*>(&u) = h; return u;
}
__device__ __forceinline__ __half2 u2h(unsigned u) {
    __half2 h; *reinterpret_cast<unsigned*>(&h) = u; return h;
}

// Scratch (__device__ globals; zero-init at load; cleanup-at-end for replays)
__device__ __half   g_xh[(size_t)KMAX * M];  // fp16 shadow of x (written pass1, read pass2)
__device__ float    g_t[KMAX];               // t_k
__device__ float    g_v1r[4][M];             // W^T a1, 4 replicas (atomic accum)
__device__ float    g_v2r[4][M];             // W^T a2, 4 replicas
__device__ float    g_colsum[M];
__device__ float    g_scal[4];               // [0]=c1+c2, [1]=C, [2]=Z
__device__ unsigned g_cnt1, g_cnt2;

// ---------------------------------------------------------------------------
// Prep: 256 CTAs x 2 W rows (coalesced float4), combine 2 rows in smem,
// atomics into replica bid&3 (64 serialized adds/address). Block 256: b-dot.
// ---------------------------------------------------------------------------
__global__ __launch_bounds__(256) void mhi_prep(const float* __restrict__ W,
                                                const float* __restrict__ b,
                                                const float* __restrict__ a,
                                                float* __restrict__ out) {
    int tid = threadIdx.x;
    if (blockIdx.x < 256) {
        int rg  = tid >> 7;          // 0/1: which of the two rows
        int c4  = tid & 127;         // float4 column index
        int row = blockIdx.x * 2 + rg;
        float4 w4 = reinterpret_cast<const float4*>(W)[row * 128 + c4];
        float A1 = __ldg(a + row);
        float A2 = __ldg(a + M + row);
        float4 s1 = {A1*w4.x, A1*w4.y, A1*w4.z, A1*w4.w};
        float4 s2 = {A2*w4.x, A2*w4.y, A2*w4.z, A2*w4.w};
        __shared__ float4 sm1[128], sm2[128];
        if (rg == 1) { sm1[c4] = s1; sm2[c4] = s2; }
        __syncthreads();
        if (rg == 0) {
            float4 o1 = sm1[c4], o2 = sm2[c4];
            s1.x += o1.x; s1.y += o1.y; s1.z += o1.z; s1.w += o1.w;
            s2.x += o2.x; s2.y += o2.y; s2.z += o2.z; s2.w += o2.w;
            int rep = blockIdx.x & 3;
            int j = c4 * 4;
            atomicAdd(&g_v1r[rep][j + 0], s1.x); atomicAdd(&g_v1r[rep][j + 1], s1.y);
            atomicAdd(&g_v1r[rep][j + 2], s1.z); atomicAdd(&g_v1r[rep][j + 3], s1.w);
            atomicAdd(&g_v2r[rep][j + 0], s2.x); atomicAdd(&g_v2r[rep][j + 1], s2.y);
            atomicAdd(&g_v2r[rep][j + 2], s2.z); atomicAdd(&g_v2r[rep][j + 3], s2.w);
        }
    } else {
        out[tid]       = 0.f;   // d_out is poisoned
        out[tid + 256] = 0.f;
        float p1 = 0.f, p2 = 0.f;
        for (int i = tid; i < M; i += 256) {
            p1 += b[i] * a[i];
            p2 += b[i] * a[M + i];
        }
        __shared__ float r1[256], r2[256];
        r1[tid] = p1; r2[tid] = p2;
        __syncthreads();
        for (int s = 128; s > 0; s >>= 1) {
            if (tid < s) { r1[tid] += r1[tid + s]; r2[tid] += r2[tid + s]; }
            __syncthreads();
        }
        if (tid == 0) g_scal[0] = r1[0] + r2[0];
    }
}

// ---------------------------------------------------------------------------
// Pass 1 (ascending): t_k = x_k . v1 ; colsum += x_k ; g_xh = fp16(x).
// x reads use __ldcs (evict-first) so the fp16 copy stays L2-resident.
// Last CTA computes C and cleans up prep accumulators.
// ---------------------------------------------------------------------------
__global__ __launch_bounds__(256) void mhi_pass1(const float* __restrict__ x, int K) {
    __shared__ float4 sv[M / 4];
    __shared__ float  scol[M];
    int tid = threadIdx.x;
    if (tid < M / 4) {
        const float4* r0 = reinterpret_cast<const float4*>(g_v1r[0]);
        const float4* r1 = reinterpret_cast<const float4*>(g_v1r[1]);
        const float4* r2 = reinterpret_cast<const float4*>(g_v1r[2]);
        const float4* r3 = reinterpret_cast<const float4*>(g_v1r[3]);
        float4 q0 = r0[tid], q1 = r1[tid], q2 = r2[tid], q3 = r3[tid];
        sv[tid] = make_float4(q0.x+q1.x+q2.x+q3.x, q0.y+q1.y+q2.y+q3.y,
                              q0.z+q1.z+q2.z+q3.z, q0.w+q1.w+q2.w+q3.w);
    }
    for (int j = tid; j < M; j += 256) scol[j] = 0.f;
    __syncthreads();

    int lane = tid & 31, w = tid >> 5;
    float4 v0 = sv[lane], v1 = sv[lane + 32], v2 = sv[lane + 64], v3 = sv[lane + 96];

    float4 a0 = {0,0,0,0}, a1 = a0, a2 = a0, a3 = a0;
    int gw = blockIdx.x * 8 + w;
    int nw = gridDim.x * 8;
    for (int k = gw * 2; k < K; k += nw * 2) {
        const float4* rA = reinterpret_cast<const float4*>(x + (size_t)k * M);
        float4 x0 = __ldcs(rA + lane),      x1 = __ldcs(rA + lane + 32),
               x2 = __ldcs(rA + lane + 64), x3 = __ldcs(rA + lane + 96);
        bool hasB = (k + 1) < K;
        const float4* rB = reinterpret_cast<const float4*>(x + (size_t)(hasB ? k + 1 : k) * M);
        float4 y0 = __ldcs(rB + lane),      y1 = __ldcs(rB + lane + 32),
               y2 = __ldcs(rB + lane + 64), y3 = __ldcs(rB + lane + 96);

        // fp16 shadow copy (8B per float4, coalesced)
        {
            uint2* hA = reinterpret_cast<uint2*>(g_xh + (size_t)k * M);
            hA[lane]      = make_uint2(h2u(__float22half2_rn({x0.x, x0.y})),
                                       h2u(__float22half2_rn({x0.z, x0.w})));
            hA[lane + 32] = make_uint2(h2u(__float22half2_rn({x1.x, x1.y})),
                                       h2u(__float22half2_rn({x1.z, x1.w})));
            hA[lane + 64] = make_uint2(h2u(__float22half2_rn({x2.x, x2.y})),
                                       h2u(__float22half2_rn({x2.z, x2.w})));
            hA[lane + 96] = make_uint2(h2u(__float22half2_rn({x3.x, x3.y})),
                                       h2u(__float22half2_rn({x3.z, x3.w})));
            if (hasB) {
                uint2* hB = reinterpret_cast<uint2*>(g_xh + (size_t)(k + 1) * M);
                hB[lane]      = make_uint2(h2u(__float22half2_rn({y0.x, y0.y})),
                                           h2u(__float22half2_rn({y0.z, y0.w})));
                hB[lane + 32] = make_uint2(h2u(__float22half2_rn({y1.x, y1.y})),
                                           h2u(__float22half2_rn({y1.z, y1.w})));
                hB[lane + 64] = make_uint2(h2u(__float22half2_rn({y2.x, y2.y})),
                                           h2u(__float22half2_rn({y2.z, y2.w})));
                hB[lane + 96] = make_uint2(h2u(__float22half2_rn({y3.x, y3.y})),
                                           h2u(__float22half2_rn({y3.z, y3.w})));
            }
        }

        float dA = x0.x*v0.x + x0.y*v0.y + x0.z*v0.z + x0.w*v0.w
                 + x1.x*v1.x + x1.y*v1.y + x1.z*v1.z + x1.w*v1.w
                 + x2.x*v2.x + x2.y*v2.y + x2.z*v2.z + x2.w*v2.w
                 + x3.x*v3.x + x3.y*v3.y + x3.z*v3.z + x3.w*v3.w;
        float dB = y0.x*v0.x + y0.y*v0.y + y0.z*v0.z + y0.w*v0.w
                 + y1.x*v1.x + y1.y*v1.y + y1.z*v1.z + y1.w*v1.w
                 + y2.x*v2.x + y2.y*v2.y + y2.z*v2.z + y2.w*v2.w
                 + y3.x*v3.x + y3.y*v3.y + y3.z*v3.z + y3.w*v3.w;
        #pragma unroll
        for (int o = 16; o; o >>= 1) {
            dA += __shfl_xor_sync(0xFFFFFFFFu, dA, o);
            dB += __shfl_xor_sync(0xFFFFFFFFu, dB, o);
        }
        if (lane == 0) {
            g_t[k] = dA;
            if (hasB) g_t[k + 1] = dB;
        }
        a0.x += x0.x; a0.y += x0.y; a0.z += x0.z; a0.w += x0.w;
        a1.x += x1.x; a1.y += x1.y; a1.z += x1.z; a1.w += x1.w;
        a2.x += x2.x; a2.y += x2.y; a2.z += x2.z; a2.w += x2.w;
        a3.x += x3.x; a3.y += x3.y; a3.z += x3.z; a3.w += x3.w;
        if (hasB) {
            a0.x += y0.x; a0.y += y0.y; a0.z += y0.z; a0.w += y0.w;
            a1.x += y1.x; a1.y += y1.y; a1.z += y1.z; a1.w += y1.w;
            a2.x += y2.x; a2.y += y2.y; a2.z += y2.z; a2.w += y2.w;
            a3.x += y3.x; a3.y += y3.y; a3.z += y3.z; a3.w += y3.w;
        }
    }
    int c = 4 * lane;
    atomicAdd(&scol[c + 0],       a0.x); atomicAdd(&scol[c + 1],       a0.y);
    atomicAdd(&scol[c + 2],       a0.z); atomicAdd(&scol[c + 3],       a0.w);
    atomicAdd(&scol[128 + c + 0], a1.x); atomicAdd(&scol[128 + c + 1], a1.y);
    atomicAdd(&scol[128 + c + 2], a1.z); atomicAdd(&scol[128 + c + 3], a1.w);
    atomicAdd(&scol[256 + c + 0], a2.x); atomicAdd(&scol[256 + c + 1], a2.y);
    atomicAdd(&scol[256 + c + 2], a2.z); atomicAdd(&scol[256 + c + 3], a2.w);
    atomicAdd(&scol[384 + c + 0], a3.x); atomicAdd(&scol[384 + c + 1], a3.y);
    atomicAdd(&scol[384 + c + 2], a3.z); atomicAdd(&scol[384 + c + 3], a3.w);
    __syncthreads();
    for (int j = tid; j < M; j += 256) atomicAdd(&g_colsum[j], scol[j]);

    // Last CTA: compute C; clean up prep/colsum accumulators for next replay.
    __shared__ bool isLast;
    __threadfence();
    __syncthreads();
    if (tid == 0) isLast = (atomicAdd(&g_cnt1, 1u) == gridDim.x - 1);
    __syncthreads();
    if (isLast) {
        float p = 0.f;
        for (int j = tid; j < M; j += 256) {
            float v2j = g_v2r[0][j] + g_v2r[1][j] + g_v2r[2][j] + g_v2r[3][j];
            p += g_colsum[j] * v2j;
        }
        #pragma unroll
        for (int o = 16; o; o >>= 1) p += __shfl_xor_sync(0xFFFFFFFFu, p, o);
        __shared__ float sp[8];
        if (lane == 0) sp[w] = p;
        __syncthreads();
        for (int j = tid; j < M; j += 256) {
            g_colsum[j] = 0.f;
            g_v1r[0][j] = 0.f; g_v1r[1][j] = 0.f; g_v1r[2][j] = 0.f; g_v1r[3][j] = 0.f;
            g_v2r[0][j] = 0.f; g_v2r[1][j] = 0.f; g_v2r[2][j] = 0.f; g_v2r[3][j] = 0.f;
        }
        if (tid == 0) {
            float s = 0.f;
            #pragma unroll
            for (int q = 0; q < 8; q++) s += sp[q];
            g_scal[1] = g_scal[0] + s * (1.0f / (float)K);
            g_cnt1 = 0u;
        }
    }
}

// ---------------------------------------------------------------------------
// Pass 2 (DESCENDING over the fp16 shadow copy, mostly L2-resident):
// w_k = exp(relu(t_k + C)); out += w_k x_k (fp32 accum); Z += w_k.
// Last CTA normalizes and cleans up.
// ---------------------------------------------------------------------------
__global__ __launch_bounds__(256) void mhi_pass2(float* __restrict__ out, int K) {
    __shared__ float scol[M];
    int tid = threadIdx.x;
    for (int j = tid; j < M; j += 256) scol[j] = 0.f;
    __syncthreads();
    float C = g_scal[1];
    int lane = tid & 31, w = tid >> 5;
    float4 a0 = {0,0,0,0}, a1 = a0, a2 = a0, a3 = a0;
    float zloc = 0.f;
    int gw = blockIdx.x * 8 + w;
    int nw = gridDim.x * 8;
    int P = (K + 1) >> 1;
    for (int p = P - 1 - gw; p >= 0; p -= nw) {
        int k = 2 * p;
        bool hasB = (k + 1) < K;
        float wA = __expf(fmaxf(g_t[k] + C, 0.f));
        float wB = hasB ? __expf(fmaxf(g_t[k + 1] + C, 0.f)) : 0.f;
        const uint2* hA = reinterpret_cast<const uint2*>(g_xh + (size_t)k * M);
        const uint2* hB = reinterpret_cast<const uint2*>(g_xh + (size_t)(hasB ? k + 1 : k) * M);
        uint2 uA0 = hA[lane], uA1 = hA[lane + 32], uA2 = hA[lane + 64], uA3 = hA[lane + 96];
        uint2 uB0 = hB[lane], uB1 = hB[lane + 32], uB2 = hB[lane + 64], uB3 = hB[lane + 96];
        {
            float2 fa0 = __half22float2(u2h(uA0.x)), fa1 = __half22float2(u2h(uA0.y));
            float2 fb0 = __half22float2(u2h(uB0.x)), fb1 = __half22float2(u2h(uB0.y));
            a0.x += wA*fa0.x + wB*fb0.x; a0.y += wA*fa0.y + wB*fb0.y;
            a0.z += wA*fa1.x + wB*fb1.x; a0.w += wA*fa1.y + wB*fb1.y;
        }
        {
            float2 fa0 = __half22float2(u2h(uA1.x)), fa1 = __half22float2(u2h(uA1.y));
            float2 fb0 = __half22float2(u2h(uB1.x)), fb1 = __half22float2(u2h(uB1.y));
            a1.x += wA*fa0.x + wB*fb0.x; a1.y += wA*fa0.y + wB*fb0.y;
            a1.z += wA*fa1.x + wB*fb1.x; a1.w += wA*fa1.y + wB*fb1.y;
        }
        {
            float2 fa0 = __half22float2(u2h(uA2.x)), fa1 = __half22float2(u2h(uA2.y));
            float2 fb0 = __half22float2(u2h(uB2.x)), fb1 = __half22float2(u2h(uB2.y));
            a2.x += wA*fa0.x + wB*fb0.x; a2.y += wA*fa0.y + wB*fb0.y;
            a2.z += wA*fa1.x + wB*fb1.x; a2.w += wA*fa1.y + wB*fb1.y;
        }
        {
            float2 fa0 = __half22float2(u2h(uA3.x)), fa1 = __half22float2(u2h(uA3.y));
            float2 fb0 = __half22float2(u2h(uB3.x)), fb1 = __half22float2(u2h(uB3.y));
            a3.x += wA*fa0.x + wB*fb0.x; a3.y += wA*fa0.y + wB*fb0.y;
            a3.z += wA*fa1.x + wB*fb1.x; a3.w += wA*fa1.y + wB*fb1.y;
        }
        zloc += wA + wB;
    }
    __shared__ float zw[8];
    if (lane == 0) zw[w] = zloc;   // identical across lanes

    int c = 4 * lane;
    atomicAdd(&scol[c + 0],       a0.x); atomicAdd(&scol[c + 1],       a0.y);
    atomicAdd(&scol[c + 2],       a0.z); atomicAdd(&scol[c + 3],       a0.w);
    atomicAdd(&scol[128 + c + 0], a1.x); atomicAdd(&scol[128 + c + 1], a1.y);
    atomicAdd(&scol[128 + c + 2], a1.z); atomicAdd(&scol[128 + c + 3], a1.w);
    atomicAdd(&scol[256 + c + 0], a2.x); atomicAdd(&scol[256 + c + 1], a2.y);
    atomicAdd(&scol[256 + c + 2], a2.z); atomicAdd(&scol[256 + c + 3], a2.w);
    atomicAdd(&scol[384 + c + 0], a3.x); atomicAdd(&scol[384 + c + 1], a3.y);
    atomicAdd(&scol[384 + c + 2], a3.z); atomicAdd(&scol[384 + c + 3], a3.w);
    __syncthreads();
    if (tid == 0) {
        float z = 0.f;
        #pragma unroll
        for (int q = 0; q < 8; q++) z += zw[q];
        atomicAdd(&g_scal[2], z);
    }
    for (int j = tid; j < M; j += 256) atomicAdd(&out[j], scol[j]);

    __shared__ bool isLast;
    __threadfence();
    __syncthreads();
    if (tid == 0) isLast = (atomicAdd(&g_cnt2, 1u) == gridDim.x - 1);
    __syncthreads();
    if (isLast) {
        float invZ = 1.0f / g_scal[2];
        for (int j = tid; j < M; j += 256) out[j] *= invZ;
        if (tid == 0) { g_scal[2] = 0.f; g_cnt2 = 0u; }
    }
}

// ---------------------------------------------------------------------------
extern "C" void kernel_launch(void* const* d_in, const int* in_sizes, int n_in,
                              void* d_out, int out_size) {
    const float* x = (const float*)d_in[0];   // [K, 512]
    const float* W = (const float*)d_in[1];   // [512, 512]
    const float* b = (const float*)d_in[2];   // [512]
    const float* a = (const float*)d_in[3];   // [1024]
    float* out = (float*)d_out;               // [512]
    int K = in_sizes[0] / M;

    mhi_prep<<<257, 256>>>(W, b, a, out);
    mhi_pass1<<<PASS_GRID, 256>>>(x, K);
    mhi_pass2<<<PASS_GRID, 256>>>(out, K);
}

// round 7
// speedup vs baseline: 1.2403x; 1.2162x over previous
#include <cuda_runtime.h>

#define M 512
#define PASS_GRID 608   // ~4 CTAs/SM

// Scratch (__device__ globals; zero-init at load; cleanup-at-end for replays)
__device__ float    g_v1r[4][M];   // W^T a1 replicas (atomic accum; zeroed by K1 last CTA)
__device__ float    g_v2r[4][M];   // W^T a2 replicas (zeroed by K1 last CTA)
__device__ float    g_v1[M];       // final v1 (plain store by K1 last CTA)
__device__ float    g_colsum[M];   // column sums (zeroed by K1 last CTA)
__device__ float    g_scal[4];     // [0]=c1+c2 (store), [1]=C (store), [2]=Z (zeroed)
__device__ unsigned g_cnt1, g_cnt2;

// ---------------------------------------------------------------------------
// K1: prep folded in (CTAs 0..255: W rows -> v replicas; CTA 256: b-dots +
// zero out), then ALL CTAs flat-stream x (pure read) for colsum.
// Last CTA: v1 = sum(replicas); C = c1+c2 + (colsum.v2)/K; cleanup.
// x is swept ascending -> its tail (~L2 capacity) stays L2-resident for K2.
// ---------------------------------------------------------------------------
__global__ __launch_bounds__(256, 4) void mhi_k1(const float* __restrict__ x,
                                                 const float* __restrict__ W,
                                                 const float* __restrict__ b,
                                                 const float* __restrict__ a,
                                                 float* __restrict__ out, int K) {
    int tid  = threadIdx.x;
    int lane = tid & 31, w = tid >> 5;
    int bid  = blockIdx.x;

    // ---- prep portion (cheap; no dependency on the streaming part) ----
    if (bid < 256) {
        int rg  = tid >> 7;          // 0/1: which of the two W rows
        int c4  = tid & 127;         // float4 column index
        int row = bid * 2 + rg;
        float4 w4 = reinterpret_cast<const float4*>(W)[row * 128 + c4];
        float A1 = __ldg(a + row);
        float A2 = __ldg(a + M + row);
        float4 s1 = {A1*w4.x, A1*w4.y, A1*w4.z, A1*w4.w};
        float4 s2 = {A2*w4.x, A2*w4.y, A2*w4.z, A2*w4.w};
        __shared__ float4 sm1[128], sm2[128];
        if (rg == 1) { sm1[c4] = s1; sm2[c4] = s2; }
        __syncthreads();
        if (rg == 0) {
            float4 o1 = sm1[c4], o2 = sm2[c4];
            s1.x += o1.x; s1.y += o1.y; s1.z += o1.z; s1.w += o1.w;
            s2.x += o2.x; s2.y += o2.y; s2.z += o2.z; s2.w += o2.w;
            int rep = bid & 3;
            int j = c4 * 4;
            atomicAdd(&g_v1r[rep][j + 0], s1.x); atomicAdd(&g_v1r[rep][j + 1], s1.y);
            atomicAdd(&g_v1r[rep][j + 2], s1.z); atomicAdd(&g_v1r[rep][j + 3], s1.w);
            atomicAdd(&g_v2r[rep][j + 0], s2.x); atomicAdd(&g_v2r[rep][j + 1], s2.y);
            atomicAdd(&g_v2r[rep][j + 2], s2.z); atomicAdd(&g_v2r[rep][j + 3], s2.w);
        }
        __syncthreads();
    } else if (bid == 256) {
        out[tid]       = 0.f;   // d_out is poisoned: zero before K2's atomics
        out[tid + 256] = 0.f;
        float p1 = 0.f, p2 = 0.f;
        for (int i = tid; i < M; i += 256) {
            p1 += b[i] * a[i];
            p2 += b[i] * a[M + i];
        }
        #pragma unroll
        for (int o = 16; o; o >>= 1) {
            p1 += __shfl_xor_sync(0xFFFFFFFFu, p1, o);
            p2 += __shfl_xor_sync(0xFFFFFFFFu, p2, o);
        }
        __shared__ float rb[16];
        if (lane == 0) { rb[w] = p1; rb[8 + w] = p2; }
        __syncthreads();
        if (tid == 0) {
            float s = 0.f;
            #pragma unroll
            for (int q = 0; q < 16; q++) s += rb[q];
            g_scal[0] = s;      // c1 + c2
        }
    }

    // ---- flat streaming colsum over x (ascending; pure read) ----
    // stride = 608*256 = 155648, divisible by 128 -> each thread's float4
    // column index is constant: c4 = tid & 127.
    __shared__ float scol[M];
    for (int j = tid; j < M; j += 256) scol[j] = 0.f;
    __syncthreads();

    const float4* X4 = reinterpret_cast<const float4*>(x);
    int N4     = K * 128;
    int stride = PASS_GRID * 256;
    int idx    = bid * 256 + tid;
    float4 acc = {0, 0, 0, 0};
    for (; idx + 3 * stride < N4; idx += 4 * stride) {
        float4 p0 = X4[idx];
        float4 p1 = X4[idx + stride];
        float4 p2 = X4[idx + 2 * stride];
        float4 p3 = X4[idx + 3 * stride];
        acc.x += (p0.x + p1.x) + (p2.x + p3.x);
        acc.y += (p0.y + p1.y) + (p2.y + p3.y);
        acc.z += (p0.z + p1.z) + (p2.z + p3.z);
        acc.w += (p0.w + p1.w) + (p2.w + p3.w);
    }
    for (; idx < N4; idx += stride) {
        float4 p = X4[idx];
        acc.x += p.x; acc.y += p.y; acc.z += p.z; acc.w += p.w;
    }
    {
        int j = (tid & 127) * 4;
        atomicAdd(&scol[j + 0], acc.x); atomicAdd(&scol[j + 1], acc.y);
        atomicAdd(&scol[j + 2], acc.z); atomicAdd(&scol[j + 3], acc.w);
    }
    __syncthreads();
    for (int j = tid; j < M; j += 256) atomicAdd(&g_colsum[j], scol[j]);

    // ---- last CTA: finalize v1, compute C, cleanup for graph replay ----
    __shared__ bool isLast;
    __threadfence();
    __syncthreads();
    if (tid == 0) isLast = (atomicAdd(&g_cnt1, 1u) == gridDim.x - 1);
    __syncthreads();
    if (isLast) {
        float p = 0.f;
        for (int j = tid; j < M; j += 256) {
            float v1j = g_v1r[0][j] + g_v1r[1][j] + g_v1r[2][j] + g_v1r[3][j];
            float v2j = g_v2r[0][j] + g_v2r[1][j] + g_v2r[2][j] + g_v2r[3][j];
            g_v1[j] = v1j;                       // plain store (overwritten each replay)
            p += g_colsum[j] * v2j;
        }
        #pragma unroll
        for (int o = 16; o; o >>= 1) p += __shfl_xor_sync(0xFFFFFFFFu, p, o);
        __shared__ float sp[8];
        if (lane == 0) sp[w] = p;
        __syncthreads();
        for (int j = tid; j < M; j += 256) {     // cleanup accumulators
            g_colsum[j] = 0.f;
            g_v1r[0][j] = 0.f; g_v1r[1][j] = 0.f; g_v1r[2][j] = 0.f; g_v1r[3][j] = 0.f;
            g_v2r[0][j] = 0.f; g_v2r[1][j] = 0.f; g_v2r[2][j] = 0.f; g_v2r[3][j] = 0.f;
        }
        if (tid == 0) {
            float s = 0.f;
            #pragma unroll
            for (int q = 0; q < 8; q++) s += sp[q];
            g_scal[1] = g_scal[0] + s * (1.0f / (float)K);   // C
            g_cnt1 = 0u;
        }
    }
}

// ---------------------------------------------------------------------------
// K2 (DESCENDING; top of x is L2-hot from K1): single set of loads per row
// serves BOTH t_k = x_k.v1 and the weighted accumulation.
// w_k = exp(relu(t_k + C)) (softmax shift-invariant; e in [0,~6], exp safe).
// out += w_k x_k; Z += w_k. Last CTA normalizes and cleans up.
// ---------------------------------------------------------------------------
__global__ __launch_bounds__(256, 4) void mhi_k2(const float* __restrict__ x,
                                                 float* __restrict__ out, int K) {
    __shared__ float4 sv[M / 4];
    __shared__ float  scol[M];
    int tid = threadIdx.x;
    if (tid < M / 4) sv[tid] = reinterpret_cast<const float4*>(g_v1)[tid];
    for (int j = tid; j < M; j += 256) scol[j] = 0.f;
    __syncthreads();

    float C = g_scal[1];
    int lane = tid & 31, w = tid >> 5;
    float4 v0 = sv[lane], v1 = sv[lane + 32], v2 = sv[lane + 64], v3 = sv[lane + 96];

    float4 a0 = {0,0,0,0}, a1 = a0, a2 = a0, a3 = a0;
    float zloc = 0.f;
    int gw = blockIdx.x * 8 + w;
    int nw = PASS_GRID * 8;
    for (int k = K - 1 - gw; k >= 0; k -= nw) {   // descending: L2-hot first
        const float4* r = reinterpret_cast<const float4*>(x + (size_t)k * M);
        float4 x0 = r[lane], x1 = r[lane + 32], x2 = r[lane + 64], x3 = r[lane + 96];
        float d = x0.x*v0.x + x0.y*v0.y + x0.z*v0.z + x0.w*v0.w
                + x1.x*v1.x + x1.y*v1.y + x1.z*v1.z + x1.w*v1.w
                + x2.x*v2.x + x2.y*v2.y + x2.z*v2.z + x2.w*v2.w
                + x3.x*v3.x + x3.y*v3.y + x3.z*v3.z + x3.w*v3.w;
        #pragma unroll
        for (int o = 16; o; o >>= 1) d += __shfl_xor_sync(0xFFFFFFFFu, d, o);
        float wk = __expf(fmaxf(d + C, 0.f));
        a0.x += wk*x0.x; a0.y += wk*x0.y; a0.z += wk*x0.z; a0.w += wk*x0.w;
        a1.x += wk*x1.x; a1.y += wk*x1.y; a1.z += wk*x1.z; a1.w += wk*x1.w;
        a2.x += wk*x2.x; a2.y += wk*x2.y; a2.z += wk*x2.z; a2.w += wk*x2.w;
        a3.x += wk*x3.x; a3.y += wk*x3.y; a3.z += wk*x3.z; a3.w += wk*x3.w;
        zloc += wk;
    }
    __shared__ float zw[8];
    if (lane == 0) zw[w] = zloc;   // zloc identical across lanes

    int c = 4 * lane;
    atomicAdd(&scol[c + 0],       a0.x); atomicAdd(&scol[c + 1],       a0.y);
    atomicAdd(&scol[c + 2],       a0.z); atomicAdd(&scol[c + 3],       a0.w);
    atomicAdd(&scol[128 + c + 0], a1.x); atomicAdd(&scol[128 + c + 1], a1.y);
    atomicAdd(&scol[128 + c + 2], a1.z); atomicAdd(&scol[128 + c + 3], a1.w);
    atomicAdd(&scol[256 + c + 0], a2.x); atomicAdd(&scol[256 + c + 1], a2.y);
    atomicAdd(&scol[256 + c + 2], a2.z); atomicAdd(&scol[256 + c + 3], a2.w);
    atomicAdd(&scol[384 + c + 0], a3.x); atomicAdd(&scol[384 + c + 1], a3.y);
    atomicAdd(&scol[384 + c + 2], a3.z); atomicAdd(&scol[384 + c + 3], a3.w);
    __syncthreads();
    if (tid == 0) {
        float z = 0.f;
        #pragma unroll
        for (int q = 0; q < 8; q++) z += zw[q];
        atomicAdd(&g_scal[2], z);
    }
    for (int j = tid; j < M; j += 256) atomicAdd(&out[j], scol[j]);

    // last CTA: normalize by Z; cleanup for next graph replay
    __shared__ bool isLast;
    __threadfence();
    __syncthreads();
    if (tid == 0) isLast = (atomicAdd(&g_cnt2, 1u) == gridDim.x - 1);
    __syncthreads();
    if (isLast) {
        float invZ = 1.0f / g_scal[2];
        for (int j = tid; j < M; j += 256) out[j] *= invZ;
        if (tid == 0) { g_scal[2] = 0.f; g_cnt2 = 0u; }
    }
}

// ---------------------------------------------------------------------------
extern "C" void kernel_launch(void* const* d_in, const int* in_sizes, int n_in,
                              void* d_out, int out_size) {
    const float* x = (const float*)d_in[0];   // [K, 512]
    const float* W = (const float*)d_in[1];   // [512, 512]
    const float* b = (const float*)d_in[2];   // [512]
    const float* a = (const float*)d_in[3];   // [1024]
    float* out = (float*)d_out;               // [512]
    int K = in_sizes[0] / M;

    mhi_k1<<<PASS_GRID, 256>>>(x, W, b, a, out, K);
    mhi_k2<<<PASS_GRID, 256>>>(x, out, K);
}